// round 10
// baseline (speedup 1.0000x reference)
#include <cuda_runtime.h>
#include <cub/cub.cuh>
#include <cstdint>

// ---------------------------------------------------------------------------
// NbitTreeEncoder under JAX x64-DISABLED semantics (confirmed rel_err=0.0):
// int32 codes (Q2's <<32 vanishes), signed sort, sign-fill arithmetic shifts
// for layer shifts >= 32, left shifts >= 32 produce 0 in the bit permutation.
// Output (float32): flags[16*N], counts[16], permute[48], offset[3], scale[3].
// ---------------------------------------------------------------------------

#define NMAX 1000000
#define TB 256
#define FULLMASK 0xffffffffu

__device__ float g_off[3], g_scl[3];
__device__ int g_perm[48];
__device__ int g_counts[16];
__device__ float g_mm[4096 * 6];                          // per-block min/max scratch
__device__ int g_onescr[4096 * 32];                       // per-block bit-pop scratch
__device__ unsigned int g_code[NMAX];                     // pre-sort (biased) codes
__device__ unsigned int g_sorted[NMAX];
__device__ unsigned char g_L[NMAX];
__device__ int g_blk[16 * 4096];                          // per-(layer,block) bases
__device__ unsigned int g_flagsb[(size_t)16 * NMAX / 4];  // byte-packed flags
__device__ unsigned char g_temp[64 * 1024 * 1024];        // CUB scratch

// child slot at layer l for biased code u (u = signed_code ^ 0x80000000)
__device__ __forceinline__ unsigned child_at(unsigned u, int l) {
    unsigned cb31 = ((~u) >> 31) & 1u;          // original sign bit of code
    if (l <= 4) return cb31 ? 7u : 0u;          // shift >= 33: sign-fill
    if (l == 5) return 6u * cb31 + ((u >> 30) & 1u);  // shift 30 spans sign
    return (u >> (45 - 3 * l)) & 7u;            // shift <= 27: plain bits
}

// ---------------- kernels ----------------

// per-block min/max -> scratch (no atomics, no init kernel)
__global__ void k_minmax(const float* __restrict__ X, int n) {
    int i = blockIdx.x * blockDim.x + threadIdx.x;
    float inf = __int_as_float(0x7f800000);
    float v0 = inf, v1 = inf, v2 = inf;
    float w0 = -inf, w1 = -inf, w2 = -inf;
    if (i < n) {
        v0 = w0 = X[3 * i + 0];
        v1 = w1 = X[3 * i + 1];
        v2 = w2 = X[3 * i + 2];
    }
    for (int o = 16; o; o >>= 1) {
        v0 = fminf(v0, __shfl_down_sync(FULLMASK, v0, o));
        v1 = fminf(v1, __shfl_down_sync(FULLMASK, v1, o));
        v2 = fminf(v2, __shfl_down_sync(FULLMASK, v2, o));
        w0 = fmaxf(w0, __shfl_down_sync(FULLMASK, w0, o));
        w1 = fmaxf(w1, __shfl_down_sync(FULLMASK, w1, o));
        w2 = fmaxf(w2, __shfl_down_sync(FULLMASK, w2, o));
    }
    __shared__ float s[8][6];
    int lane = threadIdx.x & 31, wid = threadIdx.x >> 5;
    if (lane == 0) {
        s[wid][0] = v0; s[wid][1] = v1; s[wid][2] = v2;
        s[wid][3] = w0; s[wid][4] = w1; s[wid][5] = w2;
    }
    __syncthreads();
    if (threadIdx.x == 0) {
        for (int w = 1; w < 8; w++) {
            s[0][0] = fminf(s[0][0], s[w][0]);
            s[0][1] = fminf(s[0][1], s[w][1]);
            s[0][2] = fminf(s[0][2], s[w][2]);
            s[0][3] = fmaxf(s[0][3], s[w][3]);
            s[0][4] = fmaxf(s[0][4], s[w][4]);
            s[0][5] = fmaxf(s[0][5], s[w][5]);
        }
        #pragma unroll
        for (int k = 0; k < 6; k++) g_mm[blockIdx.x * 6 + k] = s[0][k];
    }
}

// single block: reduce per-block min/max, compute offset & scale
__global__ void k_params(int B) {
    float inf = __int_as_float(0x7f800000);
    float v0 = inf, v1 = inf, v2 = inf;
    float w0 = -inf, w1 = -inf, w2 = -inf;
    for (int b = threadIdx.x; b < B; b += TB) {
        v0 = fminf(v0, g_mm[b * 6 + 0]);
        v1 = fminf(v1, g_mm[b * 6 + 1]);
        v2 = fminf(v2, g_mm[b * 6 + 2]);
        w0 = fmaxf(w0, g_mm[b * 6 + 3]);
        w1 = fmaxf(w1, g_mm[b * 6 + 4]);
        w2 = fmaxf(w2, g_mm[b * 6 + 5]);
    }
    for (int o = 16; o; o >>= 1) {
        v0 = fminf(v0, __shfl_down_sync(FULLMASK, v0, o));
        v1 = fminf(v1, __shfl_down_sync(FULLMASK, v1, o));
        v2 = fminf(v2, __shfl_down_sync(FULLMASK, v2, o));
        w0 = fmaxf(w0, __shfl_down_sync(FULLMASK, w0, o));
        w1 = fmaxf(w1, __shfl_down_sync(FULLMASK, w1, o));
        w2 = fmaxf(w2, __shfl_down_sync(FULLMASK, w2, o));
    }
    __shared__ float s[8][6];
    int lane = threadIdx.x & 31, wid = threadIdx.x >> 5;
    if (lane == 0) {
        s[wid][0] = v0; s[wid][1] = v1; s[wid][2] = v2;
        s[wid][3] = w0; s[wid][4] = w1; s[wid][5] = w2;
    }
    __syncthreads();
    if (threadIdx.x == 0) {
        for (int w = 1; w < 8; w++) {
            s[0][0] = fminf(s[0][0], s[w][0]);
            s[0][1] = fminf(s[0][1], s[w][1]);
            s[0][2] = fminf(s[0][2], s[w][2]);
            s[0][3] = fmaxf(s[0][3], s[w][3]);
            s[0][4] = fmaxf(s[0][4], s[w][4]);
            s[0][5] = fmaxf(s[0][5], s[w][5]);
        }
        #pragma unroll
        for (int a = 0; a < 3; a++) {
            float off = -s[0][a];
            g_off[a] = off;
            float m = s[0][3 + a] + off;          // == max(X+offset), monotone FP
            g_scl[a] = 65535.0f / (m == 0.0f ? 1.0f : m);
        }
    }
}

// quantize + pack int32 code + per-block bit-pop (lane-owned ballots, no atomics)
__global__ void k_quant(const float* __restrict__ X, int n) {
    __shared__ float sx[TB * 3];
    __shared__ int swcnt[8][32];
    int base = blockIdx.x * TB * 3;
    int lim = 3 * n - base;
    for (int t = threadIdx.x; t < TB * 3; t += TB)
        if (t < lim) sx[t] = X[base + t];
    __syncthreads();

    int i = blockIdx.x * TB + threadIdx.x;
    int lane = threadIdx.x & 31, wid = threadIdx.x >> 5;
    unsigned c = 0;
    if (i < n) {
        float x0 = sx[3 * threadIdx.x + 0];
        float x1 = sx[3 * threadIdx.x + 1];
        unsigned q0 = (unsigned)(int)rintf((x0 + g_off[0]) * g_scl[0]);
        unsigned q1 = (unsigned)(int)rintf((x1 + g_off[1]) * g_scl[1]);
        c = q0 + (q1 << 16);   // Q2 << 32 == 0 under int32 semantics
        g_code[i] = c;
    }
    unsigned mine = 0;
    #pragma unroll
    for (int j = 0; j < 32; j++) {
        unsigned b = __ballot_sync(FULLMASK, (c >> j) & 1u);
        if (lane == j) mine = b;
    }
    swcnt[wid][lane] = __popc(mine);   // count of bit 'lane' in this warp
    __syncthreads();
    if (threadIdx.x < 32) {
        int s = 0;
        #pragma unroll
        for (int w = 0; w < 8; w++) s += swcnt[w][threadIdx.x];
        g_onescr[blockIdx.x * 32 + threadIdx.x] = s;
    }
}

// single block: reduce bit-pops, parallel stable argsort of skew scores
__global__ void k_perm(int n, int B) {
    __shared__ int ssum[8][32];
    __shared__ int sOnes[32];
    __shared__ long long sc[48];
    int bin = threadIdx.x & 31, part = threadIdx.x >> 5;
    int s = 0;
    for (int b = part; b < B; b += 8) s += g_onescr[b * 32 + bin];
    ssum[part][bin] = s;
    __syncthreads();
    if (threadIdx.x < 32) {
        int t = 0;
        #pragma unroll
        for (int p = 0; p < 8; p++) t += ssum[p][threadIdx.x];
        sOnes[threadIdx.x] = t;
    }
    __syncthreads();
    if (threadIdx.x < 48) {
        int j = threadIdx.x;
        long long o = (long long)sOnes[j < 32 ? j : 31];   // bits 32..47 = sign
        long long s2 = (long long)n - o;
        sc[j] = o > s2 ? o : s2;
    }
    __syncthreads();
    if (threadIdx.x < 48) {
        int j = threadIdx.x;
        long long v = sc[j];
        int rank = 0;
        #pragma unroll
        for (int k = 0; k < 48; k++)
            if (sc[k] < v || (sc[k] == v && k < j)) rank++;
        g_perm[rank] = j;    // argsort(score)[rank] = j  (stable)
    }
}

// bit j -> position perm[j]; dests >= 32 vanish; sources >= 32 read sign bit.
// Bias for signed sort: ucode = code ^ 0x80000000.
__global__ void k_remap(int n) {
    __shared__ int sp[48];
    if (threadIdx.x < 48) sp[threadIdx.x] = g_perm[threadIdx.x];
    __syncthreads();
    int i = blockIdx.x * blockDim.x + threadIdx.x;
    if (i < n) {
        unsigned c = g_code[i];
        unsigned sign = (c >> 31) & 1u;
        unsigned nc = 0;
        #pragma unroll
        for (int j = 0; j < 48; j++) {
            int d = sp[j];
            if (d <= 31) {
                unsigned bit = (j <= 31) ? ((c >> j) & 1u) : sign;
                nc |= bit << d;
            }
        }
        g_code[i] = nc ^ 0x80000000u;
    }
}

// fused: L[i] (first-boundary layer) + per-(layer,block) counts of (L <= l)
__global__ void k_blkcnt(int n, int B) {
    __shared__ int hist[18];
    if (threadIdx.x < 18) hist[threadIdx.x] = 0;
    __syncthreads();
    int i = blockIdx.x * TB + threadIdx.x;
    if (i < n) {
        int L = 17;
        if (i > 0) {
            unsigned d = g_sorted[i] ^ g_sorted[i - 1];
            if (d) {
                int hb = 31 - __clz(d);
                L = (hb == 31) ? 1 : (50 - hb) / 3;   // ceil((48-hb)/3)
            }
        }
        g_L[i] = (unsigned char)L;
        atomicAdd(&hist[L], 1);
    }
    __syncthreads();
    if (threadIdx.x < 16) {
        int s = 0;
        for (int k = 1; k <= threadIdx.x; k++) s += hist[k];
        g_blk[threadIdx.x * B + blockIdx.x] = s;
    }
}

// exclusive scan over blocks per layer (grid = 16 blocks, one per layer)
__global__ void k_blkscan(int B) {
    typedef cub::BlockScan<int, TB> BS;
    __shared__ typename BS::TempStorage ts;
    int l = blockIdx.x;
    int run = 0;
    for (int s = 0; s < B; s += TB) {
        int idx = s + threadIdx.x;
        int v = (idx < B) ? g_blk[l * B + idx] : 0;
        int ex, agg;
        BS(ts).ExclusiveSum(v, ex, agg);
        __syncthreads();
        if (idx < B) g_blk[l * B + idx] = run + ex;
        run += agg;
        __syncthreads();
    }
    if (threadIdx.x == 0) g_counts[l] = run + 1;
}

// all 16 layers: rank = base + prefix of (L<=l); OR child bit into flags
__global__ void k_flags_all(int n, int B) {
    __shared__ int s_base[16];
    __shared__ int s_w[16][8];
    int b = blockIdx.x;
    if (threadIdx.x < 16) s_base[threadIdx.x] = g_blk[threadIdx.x * B + b];
    int i = b * TB + threadIdx.x;
    int lane = threadIdx.x & 31, wid = threadIdx.x >> 5;
    bool act = i < n;
    int L = act ? (int)g_L[i] : 100;
    unsigned u = act ? g_sorted[i] : 0u;
    unsigned lm_le = (lane == 31) ? FULLMASK : ((2u << lane) - 1);

    unsigned bal[16];
    #pragma unroll
    for (int l = 0; l < 16; l++) {
        bal[l] = __ballot_sync(FULLMASK, L <= l);
        if (lane == 0) s_w[l][wid] = __popc(bal[l]);
    }
    __syncthreads();
    if (threadIdx.x < 16) {
        int l = threadIdx.x, run = 0;
        #pragma unroll
        for (int w = 0; w < 8; w++) { int v = s_w[l][w]; s_w[l][w] = run; run += v; }
    }
    __syncthreads();

    #pragma unroll
    for (int l = 0; l < 16; l++) {
        int r = act ? (s_base[l] + s_w[l][wid] + __popc(bal[l] & lm_le))
                    : 0x7fffffff;
        unsigned v = 1u << child_at(u, l);
        #pragma unroll
        for (int o = 1; o < 32; o <<= 1) {
            unsigned uv = __shfl_up_sync(FULLMASK, v, o);
            int ur = __shfl_up_sync(FULLMASK, r, o);
            if (lane >= o && ur == r) v |= uv;
        }
        int rn = __shfl_down_sync(FULLMASK, r, 1);
        if (act && (lane == 31 || rn != r)) {
            size_t byte = (size_t)l * n + r;
            atomicOr(&g_flagsb[byte >> 2], v << ((byte & 3) * 8));
        }
    }
}

// byte-packed flags -> float32 output; block 0 also writes the tail
__global__ void k_out(float* __restrict__ out, int n, size_t words,
                      long long out_size) {
    size_t w = (size_t)blockIdx.x * blockDim.x + threadIdx.x;
    if (w < words) {
        unsigned v = g_flagsb[w];
        float4 f;
        f.x = (float)(v & 0xff);
        f.y = (float)((v >> 8) & 0xff);
        f.z = (float)((v >> 16) & 0xff);
        f.w = (float)(v >> 24);
        ((float4*)out)[w] = f;
    }
    if (blockIdx.x == 0 && threadIdx.x < 70) {
        long long base = (long long)16 * n;
        if (base + 70 <= out_size) {
            int t = threadIdx.x;
            float val;
            if (t < 16)      val = (float)g_counts[t];
            else if (t < 64) val = (float)g_perm[t - 16];
            else if (t < 67) val = g_off[t - 64];
            else             val = g_scl[t - 67];
            out[base + t] = val;
        }
    }
}

// ---------------- launcher ----------------

extern "C" void kernel_launch(void* const* d_in, const int* in_sizes, int n_in,
                              void* d_out, int out_size) {
    const float* X = (const float*)d_in[0];
    int n = in_sizes[0] / 3;
    if (n > NMAX) n = NMAX;
    float* out = (float*)d_out;

    void *p_code, *p_sorted, *p_flagsb, *p_temp;
    cudaGetSymbolAddress(&p_code, g_code);
    cudaGetSymbolAddress(&p_sorted, g_sorted);
    cudaGetSymbolAddress(&p_flagsb, g_flagsb);
    cudaGetSymbolAddress(&p_temp, g_temp);

    int blocks = (n + TB - 1) / TB;
    int B = blocks;

    k_minmax<<<blocks, TB>>>(X, n);
    k_params<<<1, TB>>>(B);
    k_quant<<<blocks, TB>>>(X, n);
    k_perm<<<1, TB>>>(n, B);
    k_remap<<<blocks, TB>>>(n);

    size_t tb = sizeof(g_temp);
    cub::DeviceRadixSort::SortKeys(p_temp, tb,
                                   (const unsigned int*)p_code,
                                   (unsigned int*)p_sorted,
                                   n, 0, 32, (cudaStream_t)0);

    cudaMemsetAsync(p_flagsb, 0, (size_t)16 * n, 0);
    k_blkcnt<<<blocks, TB>>>(n, B);
    k_blkscan<<<16, TB>>>(B);
    k_flags_all<<<blocks, TB>>>(n, B);

    size_t words = (size_t)16 * n / 4;   // 16n divisible by 4
    int fb = (int)((words + TB - 1) / TB);
    k_out<<<fb, TB>>>(out, n, words, (long long)out_size);
}

// round 11
// speedup vs baseline: 1.5882x; 1.5882x over previous
#include <cuda_runtime.h>
#include <cub/cub.cuh>
#include <cstdint>

// ---------------------------------------------------------------------------
// NbitTreeEncoder under JAX x64-DISABLED semantics (confirmed rel_err=0.0):
// int32 codes (Q2's <<32 vanishes), signed sort, sign-fill arithmetic shifts
// for layer shifts >= 32, left shifts >= 32 produce 0 in the bit permutation.
// Output (float32): flags[16*N], counts[16], permute[48], offset[3], scale[3].
// ---------------------------------------------------------------------------

#define NMAX 1000000
#define TB 256
#define BSTRIDE 4096
#define FULLMASK 0xffffffffu

__device__ float g_off[3], g_scl[3];
__device__ int g_perm[48];
__device__ int g_counts[16];
__device__ int g_ones32[32];
__device__ float g_mm[4096 * 6];                          // per-block min/max scratch
__device__ int g_onescr[32 * BSTRIDE];                    // transposed bit-pop scratch
__device__ unsigned int g_code[NMAX];                     // pre-sort (biased) codes
__device__ unsigned int g_sorted[NMAX];
__device__ unsigned char g_L[NMAX];
__device__ int g_blk[16 * 4096];                          // per-(layer,block) bases
__device__ unsigned int g_flagsb[(size_t)16 * NMAX / 4];  // byte-packed flags
__device__ unsigned char g_temp[64 * 1024 * 1024];        // CUB scratch

// child slot at layer l for biased code u (u = signed_code ^ 0x80000000)
__device__ __forceinline__ unsigned child_at(unsigned u, int l) {
    unsigned cb31 = ((~u) >> 31) & 1u;          // original sign bit of code
    if (l <= 4) return cb31 ? 7u : 0u;          // shift >= 33: sign-fill
    if (l == 5) return 6u * cb31 + ((u >> 30) & 1u);  // shift 30 spans sign
    return (u >> (45 - 3 * l)) & 7u;            // shift <= 27: plain bits
}

// ---------------- kernels ----------------

// per-block min/max -> scratch (no atomics, no init kernel)
__global__ void k_minmax(const float* __restrict__ X, int n) {
    int i = blockIdx.x * blockDim.x + threadIdx.x;
    float inf = __int_as_float(0x7f800000);
    float v0 = inf, v1 = inf, v2 = inf;
    float w0 = -inf, w1 = -inf, w2 = -inf;
    if (i < n) {
        v0 = w0 = X[3 * i + 0];
        v1 = w1 = X[3 * i + 1];
        v2 = w2 = X[3 * i + 2];
    }
    for (int o = 16; o; o >>= 1) {
        v0 = fminf(v0, __shfl_down_sync(FULLMASK, v0, o));
        v1 = fminf(v1, __shfl_down_sync(FULLMASK, v1, o));
        v2 = fminf(v2, __shfl_down_sync(FULLMASK, v2, o));
        w0 = fmaxf(w0, __shfl_down_sync(FULLMASK, w0, o));
        w1 = fmaxf(w1, __shfl_down_sync(FULLMASK, w1, o));
        w2 = fmaxf(w2, __shfl_down_sync(FULLMASK, w2, o));
    }
    __shared__ float s[8][6];
    int lane = threadIdx.x & 31, wid = threadIdx.x >> 5;
    if (lane == 0) {
        s[wid][0] = v0; s[wid][1] = v1; s[wid][2] = v2;
        s[wid][3] = w0; s[wid][4] = w1; s[wid][5] = w2;
    }
    __syncthreads();
    if (threadIdx.x == 0) {
        for (int w = 1; w < 8; w++) {
            s[0][0] = fminf(s[0][0], s[w][0]);
            s[0][1] = fminf(s[0][1], s[w][1]);
            s[0][2] = fminf(s[0][2], s[w][2]);
            s[0][3] = fmaxf(s[0][3], s[w][3]);
            s[0][4] = fmaxf(s[0][4], s[w][4]);
            s[0][5] = fmaxf(s[0][5], s[w][5]);
        }
        #pragma unroll
        for (int k = 0; k < 6; k++) g_mm[blockIdx.x * 6 + k] = s[0][k];
    }
}

// single block: reduce per-block min/max, compute offset & scale
__global__ void k_params(int B) {
    float inf = __int_as_float(0x7f800000);
    float v0 = inf, v1 = inf, v2 = inf;
    float w0 = -inf, w1 = -inf, w2 = -inf;
    for (int b = threadIdx.x; b < B; b += TB) {
        v0 = fminf(v0, g_mm[b * 6 + 0]);
        v1 = fminf(v1, g_mm[b * 6 + 1]);
        v2 = fminf(v2, g_mm[b * 6 + 2]);
        w0 = fmaxf(w0, g_mm[b * 6 + 3]);
        w1 = fmaxf(w1, g_mm[b * 6 + 4]);
        w2 = fmaxf(w2, g_mm[b * 6 + 5]);
    }
    for (int o = 16; o; o >>= 1) {
        v0 = fminf(v0, __shfl_down_sync(FULLMASK, v0, o));
        v1 = fminf(v1, __shfl_down_sync(FULLMASK, v1, o));
        v2 = fminf(v2, __shfl_down_sync(FULLMASK, v2, o));
        w0 = fmaxf(w0, __shfl_down_sync(FULLMASK, w0, o));
        w1 = fmaxf(w1, __shfl_down_sync(FULLMASK, w1, o));
        w2 = fmaxf(w2, __shfl_down_sync(FULLMASK, w2, o));
    }
    __shared__ float s[8][6];
    int lane = threadIdx.x & 31, wid = threadIdx.x >> 5;
    if (lane == 0) {
        s[wid][0] = v0; s[wid][1] = v1; s[wid][2] = v2;
        s[wid][3] = w0; s[wid][4] = w1; s[wid][5] = w2;
    }
    __syncthreads();
    if (threadIdx.x == 0) {
        for (int w = 1; w < 8; w++) {
            s[0][0] = fminf(s[0][0], s[w][0]);
            s[0][1] = fminf(s[0][1], s[w][1]);
            s[0][2] = fminf(s[0][2], s[w][2]);
            s[0][3] = fmaxf(s[0][3], s[w][3]);
            s[0][4] = fmaxf(s[0][4], s[w][4]);
            s[0][5] = fmaxf(s[0][5], s[w][5]);
        }
        #pragma unroll
        for (int a = 0; a < 3; a++) {
            float off = -s[0][a];
            g_off[a] = off;
            float m = s[0][3 + a] + off;          // == max(X+offset), monotone FP
            g_scl[a] = 65535.0f / (m == 0.0f ? 1.0f : m);
        }
    }
}

// quantize + pack int32 code + per-block bit-pop (lane-owned ballots, no atomics)
// scratch is TRANSPOSED: g_onescr[bin * BSTRIDE + block] so k_red coalesces.
__global__ void k_quant(const float* __restrict__ X, int n) {
    __shared__ float sx[TB * 3];
    __shared__ int swcnt[8][32];
    int base = blockIdx.x * TB * 3;
    int lim = 3 * n - base;
    for (int t = threadIdx.x; t < TB * 3; t += TB)
        if (t < lim) sx[t] = X[base + t];
    __syncthreads();

    int i = blockIdx.x * TB + threadIdx.x;
    int lane = threadIdx.x & 31, wid = threadIdx.x >> 5;
    unsigned c = 0;
    if (i < n) {
        float x0 = sx[3 * threadIdx.x + 0];
        float x1 = sx[3 * threadIdx.x + 1];
        unsigned q0 = (unsigned)(int)rintf((x0 + g_off[0]) * g_scl[0]);
        unsigned q1 = (unsigned)(int)rintf((x1 + g_off[1]) * g_scl[1]);
        c = q0 + (q1 << 16);   // Q2 << 32 == 0 under int32 semantics
        g_code[i] = c;
    }
    unsigned mine = 0;
    #pragma unroll
    for (int j = 0; j < 32; j++) {
        unsigned b = __ballot_sync(FULLMASK, (c >> j) & 1u);
        if (lane == j) mine = b;
    }
    swcnt[wid][lane] = __popc(mine);   // count of bit 'lane' in this warp
    __syncthreads();
    if (threadIdx.x < 32) {
        int s = 0;
        #pragma unroll
        for (int w = 0; w < 8; w++) s += swcnt[w][threadIdx.x];
        g_onescr[threadIdx.x * BSTRIDE + blockIdx.x] = s;
    }
}

// grid = 32 blocks, one per bin: coalesced sum of that bin's column
__global__ void k_red(int B) {
    int bin = blockIdx.x;
    int s = 0;
    for (int b = threadIdx.x; b < B; b += TB)
        s += g_onescr[bin * BSTRIDE + b];
    for (int o = 16; o; o >>= 1) s += __shfl_down_sync(FULLMASK, s, o);
    __shared__ int sw[8];
    int lane = threadIdx.x & 31, wid = threadIdx.x >> 5;
    if (lane == 0) sw[wid] = s;
    __syncthreads();
    if (threadIdx.x == 0) {
        int t = 0;
        #pragma unroll
        for (int w = 0; w < 8; w++) t += sw[w];
        g_ones32[bin] = t;
    }
}

// single small block: stable argsort of skew scores (reads 32 ints only)
__global__ void k_perm(int n) {
    __shared__ long long sc[48];
    if (threadIdx.x < 48) {
        int j = threadIdx.x;
        long long o = (long long)g_ones32[j < 32 ? j : 31];  // bits 32..47 = sign
        long long s2 = (long long)n - o;
        sc[j] = o > s2 ? o : s2;
    }
    __syncthreads();
    if (threadIdx.x < 48) {
        int j = threadIdx.x;
        long long v = sc[j];
        int rank = 0;
        #pragma unroll
        for (int k = 0; k < 48; k++)
            if (sc[k] < v || (sc[k] == v && k < j)) rank++;
        g_perm[rank] = j;    // argsort(score)[rank] = j  (stable)
    }
}

// bit j -> position perm[j]; dests >= 32 vanish; sources >= 32 read sign bit.
// Bias for signed sort: ucode = code ^ 0x80000000.
__global__ void k_remap(int n) {
    __shared__ int sp[48];
    if (threadIdx.x < 48) sp[threadIdx.x] = g_perm[threadIdx.x];
    __syncthreads();
    int i = blockIdx.x * blockDim.x + threadIdx.x;
    if (i < n) {
        unsigned c = g_code[i];
        unsigned sign = (c >> 31) & 1u;
        unsigned nc = 0;
        #pragma unroll
        for (int j = 0; j < 48; j++) {
            int d = sp[j];
            if (d <= 31) {
                unsigned bit = (j <= 31) ? ((c >> j) & 1u) : sign;
                nc |= bit << d;
            }
        }
        g_code[i] = nc ^ 0x80000000u;
    }
}

// fused: L[i] (first-boundary layer) + per-(layer,block) counts of (L <= l)
__global__ void k_blkcnt(int n, int B) {
    __shared__ int hist[18];
    if (threadIdx.x < 18) hist[threadIdx.x] = 0;
    __syncthreads();
    int i = blockIdx.x * TB + threadIdx.x;
    if (i < n) {
        int L = 17;
        if (i > 0) {
            unsigned d = g_sorted[i] ^ g_sorted[i - 1];
            if (d) {
                int hb = 31 - __clz(d);
                L = (hb == 31) ? 1 : (50 - hb) / 3;   // ceil((48-hb)/3)
            }
        }
        g_L[i] = (unsigned char)L;
        atomicAdd(&hist[L], 1);
    }
    __syncthreads();
    if (threadIdx.x < 16) {
        int s = 0;
        for (int k = 1; k <= threadIdx.x; k++) s += hist[k];
        g_blk[threadIdx.x * B + blockIdx.x] = s;
    }
}

// exclusive scan over blocks per layer (grid = 16 blocks, one per layer)
__global__ void k_blkscan(int B) {
    typedef cub::BlockScan<int, TB> BS;
    __shared__ typename BS::TempStorage ts;
    int l = blockIdx.x;
    int run = 0;
    for (int s = 0; s < B; s += TB) {
        int idx = s + threadIdx.x;
        int v = (idx < B) ? g_blk[l * B + idx] : 0;
        int ex, agg;
        BS(ts).ExclusiveSum(v, ex, agg);
        __syncthreads();
        if (idx < B) g_blk[l * B + idx] = run + ex;
        run += agg;
        __syncthreads();
    }
    if (threadIdx.x == 0) g_counts[l] = run + 1;
}

// all 16 layers: rank = base + prefix of (L<=l); OR child bit into flags
__global__ void k_flags_all(int n, int B) {
    __shared__ int s_base[16];
    __shared__ int s_w[16][8];
    int b = blockIdx.x;
    if (threadIdx.x < 16) s_base[threadIdx.x] = g_blk[threadIdx.x * B + b];
    int i = b * TB + threadIdx.x;
    int lane = threadIdx.x & 31, wid = threadIdx.x >> 5;
    bool act = i < n;
    int L = act ? (int)g_L[i] : 100;
    unsigned u = act ? g_sorted[i] : 0u;
    unsigned lm_le = (lane == 31) ? FULLMASK : ((2u << lane) - 1);

    unsigned bal[16];
    #pragma unroll
    for (int l = 0; l < 16; l++) {
        bal[l] = __ballot_sync(FULLMASK, L <= l);
        if (lane == 0) s_w[l][wid] = __popc(bal[l]);
    }
    __syncthreads();
    if (threadIdx.x < 16) {
        int l = threadIdx.x, run = 0;
        #pragma unroll
        for (int w = 0; w < 8; w++) { int v = s_w[l][w]; s_w[l][w] = run; run += v; }
    }
    __syncthreads();

    #pragma unroll
    for (int l = 0; l < 16; l++) {
        int r = act ? (s_base[l] + s_w[l][wid] + __popc(bal[l] & lm_le))
                    : 0x7fffffff;
        unsigned v = 1u << child_at(u, l);
        #pragma unroll
        for (int o = 1; o < 32; o <<= 1) {
            unsigned uv = __shfl_up_sync(FULLMASK, v, o);
            int ur = __shfl_up_sync(FULLMASK, r, o);
            if (lane >= o && ur == r) v |= uv;
        }
        int rn = __shfl_down_sync(FULLMASK, r, 1);
        if (act && (lane == 31 || rn != r)) {
            size_t byte = (size_t)l * n + r;
            atomicOr(&g_flagsb[byte >> 2], v << ((byte & 3) * 8));
        }
    }
}

// byte-packed flags -> float32 output; block 0 also writes the tail
__global__ void k_out(float* __restrict__ out, int n, size_t words,
                      long long out_size) {
    size_t w = (size_t)blockIdx.x * blockDim.x + threadIdx.x;
    if (w < words) {
        unsigned v = g_flagsb[w];
        float4 f;
        f.x = (float)(v & 0xff);
        f.y = (float)((v >> 8) & 0xff);
        f.z = (float)((v >> 16) & 0xff);
        f.w = (float)(v >> 24);
        ((float4*)out)[w] = f;
    }
    if (blockIdx.x == 0 && threadIdx.x < 70) {
        long long base = (long long)16 * n;
        if (base + 70 <= out_size) {
            int t = threadIdx.x;
            float val;
            if (t < 16)      val = (float)g_counts[t];
            else if (t < 64) val = (float)g_perm[t - 16];
            else if (t < 67) val = g_off[t - 64];
            else             val = g_scl[t - 67];
            out[base + t] = val;
        }
    }
}

// ---------------- launcher ----------------

extern "C" void kernel_launch(void* const* d_in, const int* in_sizes, int n_in,
                              void* d_out, int out_size) {
    const float* X = (const float*)d_in[0];
    int n = in_sizes[0] / 3;
    if (n > NMAX) n = NMAX;
    float* out = (float*)d_out;

    void *p_code, *p_sorted, *p_flagsb, *p_temp;
    cudaGetSymbolAddress(&p_code, g_code);
    cudaGetSymbolAddress(&p_sorted, g_sorted);
    cudaGetSymbolAddress(&p_flagsb, g_flagsb);
    cudaGetSymbolAddress(&p_temp, g_temp);

    int blocks = (n + TB - 1) / TB;
    int B = blocks;

    k_minmax<<<blocks, TB>>>(X, n);
    k_params<<<1, TB>>>(B);
    k_quant<<<blocks, TB>>>(X, n);
    k_red<<<32, TB>>>(B);
    k_perm<<<1, 64>>>(n);
    k_remap<<<blocks, TB>>>(n);

    size_t tb = sizeof(g_temp);
    cub::DeviceRadixSort::SortKeys(p_temp, tb,
                                   (const unsigned int*)p_code,
                                   (unsigned int*)p_sorted,
                                   n, 0, 32, (cudaStream_t)0);

    cudaMemsetAsync(p_flagsb, 0, (size_t)16 * n, 0);
    k_blkcnt<<<blocks, TB>>>(n, B);
    k_blkscan<<<16, TB>>>(B);
    k_flags_all<<<blocks, TB>>>(n, B);

    size_t words = (size_t)16 * n / 4;   // 16n divisible by 4
    int fb = (int)((words + TB - 1) / TB);
    k_out<<<fb, TB>>>(out, n, words, (long long)out_size);
}

// round 12
// speedup vs baseline: 1.6089x; 1.0130x over previous
#include <cuda_runtime.h>
#include <cub/cub.cuh>
#include <cstdint>

// ---------------------------------------------------------------------------
// NbitTreeEncoder under JAX x64-DISABLED semantics (confirmed rel_err=0.0):
// int32 codes (Q2's <<32 vanishes), signed sort, sign-fill arithmetic shifts
// for layer shifts >= 32, left shifts >= 32 produce 0 in the bit permutation.
// Output (float32): flags[16*N], counts[16], permute[48], offset[3], scale[3].
// ---------------------------------------------------------------------------

#define NMAX 1000000
#define TB 256
#define FULLMASK 0xffffffffu

__device__ float g_off[3], g_scl[3];
__device__ int g_perm[48];
__device__ int g_counts[16];
__device__ int g_ones32[32];
__device__ float g_mm[4096 * 6];                          // per-block min/max scratch
__device__ unsigned int g_code[NMAX];                     // pre-sort (biased) codes
__device__ unsigned int g_sorted[NMAX];
__device__ unsigned char g_L[NMAX];
__device__ int g_blk[16 * 4096];                          // per-(layer,block) bases
__device__ unsigned int g_flagsb[(size_t)16 * NMAX / 4];  // byte-packed flags
__device__ unsigned char g_temp[64 * 1024 * 1024];        // CUB scratch

// child slot at layer l for biased code u (u = signed_code ^ 0x80000000)
__device__ __forceinline__ unsigned child_at(unsigned u, int l) {
    unsigned cb31 = ((~u) >> 31) & 1u;          // original sign bit of code
    if (l <= 4) return cb31 ? 7u : 0u;          // shift >= 33: sign-fill
    if (l == 5) return 6u * cb31 + ((u >> 30) & 1u);  // shift 30 spans sign
    return (u >> (45 - 3 * l)) & 7u;            // shift <= 27: plain bits
}

// ---------------- kernels ----------------

// per-block min/max -> scratch (no atomics, no init kernel)
__global__ void k_minmax(const float* __restrict__ X, int n) {
    int i = blockIdx.x * blockDim.x + threadIdx.x;
    float inf = __int_as_float(0x7f800000);
    float v0 = inf, v1 = inf, v2 = inf;
    float w0 = -inf, w1 = -inf, w2 = -inf;
    if (i < n) {
        v0 = w0 = X[3 * i + 0];
        v1 = w1 = X[3 * i + 1];
        v2 = w2 = X[3 * i + 2];
    }
    for (int o = 16; o; o >>= 1) {
        v0 = fminf(v0, __shfl_down_sync(FULLMASK, v0, o));
        v1 = fminf(v1, __shfl_down_sync(FULLMASK, v1, o));
        v2 = fminf(v2, __shfl_down_sync(FULLMASK, v2, o));
        w0 = fmaxf(w0, __shfl_down_sync(FULLMASK, w0, o));
        w1 = fmaxf(w1, __shfl_down_sync(FULLMASK, w1, o));
        w2 = fmaxf(w2, __shfl_down_sync(FULLMASK, w2, o));
    }
    __shared__ float s[8][6];
    int lane = threadIdx.x & 31, wid = threadIdx.x >> 5;
    if (lane == 0) {
        s[wid][0] = v0; s[wid][1] = v1; s[wid][2] = v2;
        s[wid][3] = w0; s[wid][4] = w1; s[wid][5] = w2;
    }
    __syncthreads();
    if (threadIdx.x == 0) {
        for (int w = 1; w < 8; w++) {
            s[0][0] = fminf(s[0][0], s[w][0]);
            s[0][1] = fminf(s[0][1], s[w][1]);
            s[0][2] = fminf(s[0][2], s[w][2]);
            s[0][3] = fmaxf(s[0][3], s[w][3]);
            s[0][4] = fmaxf(s[0][4], s[w][4]);
            s[0][5] = fmaxf(s[0][5], s[w][5]);
        }
        #pragma unroll
        for (int k = 0; k < 6; k++) g_mm[blockIdx.x * 6 + k] = s[0][k];
    }
}

// single block: reduce per-block min/max, compute offset & scale;
// also zeroes g_ones32 for k_quant's atomics.
__global__ void k_params(int B) {
    if (threadIdx.x < 32) g_ones32[threadIdx.x] = 0;
    float inf = __int_as_float(0x7f800000);
    float v0 = inf, v1 = inf, v2 = inf;
    float w0 = -inf, w1 = -inf, w2 = -inf;
    for (int b = threadIdx.x; b < B; b += TB) {
        v0 = fminf(v0, g_mm[b * 6 + 0]);
        v1 = fminf(v1, g_mm[b * 6 + 1]);
        v2 = fminf(v2, g_mm[b * 6 + 2]);
        w0 = fmaxf(w0, g_mm[b * 6 + 3]);
        w1 = fmaxf(w1, g_mm[b * 6 + 4]);
        w2 = fmaxf(w2, g_mm[b * 6 + 5]);
    }
    for (int o = 16; o; o >>= 1) {
        v0 = fminf(v0, __shfl_down_sync(FULLMASK, v0, o));
        v1 = fminf(v1, __shfl_down_sync(FULLMASK, v1, o));
        v2 = fminf(v2, __shfl_down_sync(FULLMASK, v2, o));
        w0 = fmaxf(w0, __shfl_down_sync(FULLMASK, w0, o));
        w1 = fmaxf(w1, __shfl_down_sync(FULLMASK, w1, o));
        w2 = fmaxf(w2, __shfl_down_sync(FULLMASK, w2, o));
    }
    __shared__ float s[8][6];
    int lane = threadIdx.x & 31, wid = threadIdx.x >> 5;
    if (lane == 0) {
        s[wid][0] = v0; s[wid][1] = v1; s[wid][2] = v2;
        s[wid][3] = w0; s[wid][4] = w1; s[wid][5] = w2;
    }
    __syncthreads();
    if (threadIdx.x == 0) {
        for (int w = 1; w < 8; w++) {
            s[0][0] = fminf(s[0][0], s[w][0]);
            s[0][1] = fminf(s[0][1], s[w][1]);
            s[0][2] = fminf(s[0][2], s[w][2]);
            s[0][3] = fmaxf(s[0][3], s[w][3]);
            s[0][4] = fmaxf(s[0][4], s[w][4]);
            s[0][5] = fmaxf(s[0][5], s[w][5]);
        }
        #pragma unroll
        for (int a = 0; a < 3; a++) {
            float off = -s[0][a];
            g_off[a] = off;
            float m = s[0][3 + a] + off;          // == max(X+offset), monotone FP
            g_scl[a] = 65535.0f / (m == 0.0f ? 1.0f : m);
        }
    }
}

// quantize + pack int32 code + bit-pop via lane-owned ballots;
// per-block 32 sums go straight to g_ones32 (32 addresses, L2-serialized ~2us).
__global__ void k_quant(const float* __restrict__ X, int n) {
    __shared__ float sx[TB * 3];
    __shared__ int swcnt[8][32];
    int base = blockIdx.x * TB * 3;
    int lim = 3 * n - base;
    for (int t = threadIdx.x; t < TB * 3; t += TB)
        if (t < lim) sx[t] = X[base + t];
    __syncthreads();

    int i = blockIdx.x * TB + threadIdx.x;
    int lane = threadIdx.x & 31, wid = threadIdx.x >> 5;
    unsigned c = 0;
    if (i < n) {
        float x0 = sx[3 * threadIdx.x + 0];
        float x1 = sx[3 * threadIdx.x + 1];
        unsigned q0 = (unsigned)(int)rintf((x0 + g_off[0]) * g_scl[0]);
        unsigned q1 = (unsigned)(int)rintf((x1 + g_off[1]) * g_scl[1]);
        c = q0 + (q1 << 16);   // Q2 << 32 == 0 under int32 semantics
        g_code[i] = c;
    }
    unsigned mine = 0;
    #pragma unroll
    for (int j = 0; j < 32; j++) {
        unsigned b = __ballot_sync(FULLMASK, (c >> j) & 1u);
        if (lane == j) mine = b;
    }
    swcnt[wid][lane] = __popc(mine);   // count of bit 'lane' in this warp
    __syncthreads();
    if (threadIdx.x < 32) {
        int s = 0;
        #pragma unroll
        for (int w = 0; w < 8; w++) s += swcnt[w][threadIdx.x];
        if (s) atomicAdd(&g_ones32[threadIdx.x], s);
    }
}

// single small block: stable argsort of skew scores (reads 32 ints only)
__global__ void k_perm(int n) {
    __shared__ long long sc[48];
    if (threadIdx.x < 48) {
        int j = threadIdx.x;
        long long o = (long long)g_ones32[j < 32 ? j : 31];  // bits 32..47 = sign
        long long s2 = (long long)n - o;
        sc[j] = o > s2 ? o : s2;
    }
    __syncthreads();
    if (threadIdx.x < 48) {
        int j = threadIdx.x;
        long long v = sc[j];
        int rank = 0;
        #pragma unroll
        for (int k = 0; k < 48; k++)
            if (sc[k] < v || (sc[k] == v && k < j)) rank++;
        g_perm[rank] = j;    // argsort(score)[rank] = j  (stable)
    }
}

// bit j -> position perm[j]; dests >= 32 vanish; sources >= 32 read sign bit.
// Bias for signed sort: ucode = code ^ 0x80000000.
__global__ void k_remap(int n) {
    __shared__ int sp[48];
    if (threadIdx.x < 48) sp[threadIdx.x] = g_perm[threadIdx.x];
    __syncthreads();
    int i = blockIdx.x * blockDim.x + threadIdx.x;
    if (i < n) {
        unsigned c = g_code[i];
        unsigned sign = (c >> 31) & 1u;
        unsigned nc = 0;
        #pragma unroll
        for (int j = 0; j < 48; j++) {
            int d = sp[j];
            if (d <= 31) {
                unsigned bit = (j <= 31) ? ((c >> j) & 1u) : sign;
                nc |= bit << d;
            }
        }
        g_code[i] = nc ^ 0x80000000u;
    }
}

// fused: L[i] (first-boundary layer) + per-(layer,block) counts of (L <= l)
__global__ void k_blkcnt(int n, int B) {
    __shared__ int hist[18];
    if (threadIdx.x < 18) hist[threadIdx.x] = 0;
    __syncthreads();
    int i = blockIdx.x * TB + threadIdx.x;
    if (i < n) {
        int L = 17;
        if (i > 0) {
            unsigned d = g_sorted[i] ^ g_sorted[i - 1];
            if (d) {
                int hb = 31 - __clz(d);
                L = (hb == 31) ? 1 : (50 - hb) / 3;   // ceil((48-hb)/3)
            }
        }
        g_L[i] = (unsigned char)L;
        atomicAdd(&hist[L], 1);
    }
    __syncthreads();
    if (threadIdx.x < 16) {
        int s = 0;
        for (int k = 1; k <= threadIdx.x; k++) s += hist[k];
        g_blk[threadIdx.x * B + blockIdx.x] = s;
    }
}

// exclusive scan over blocks per layer (grid = 16 blocks, one per layer)
__global__ void k_blkscan(int B) {
    typedef cub::BlockScan<int, TB> BS;
    __shared__ typename BS::TempStorage ts;
    int l = blockIdx.x;
    int run = 0;
    for (int s = 0; s < B; s += TB) {
        int idx = s + threadIdx.x;
        int v = (idx < B) ? g_blk[l * B + idx] : 0;
        int ex, agg;
        BS(ts).ExclusiveSum(v, ex, agg);
        __syncthreads();
        if (idx < B) g_blk[l * B + idx] = run + ex;
        run += agg;
        __syncthreads();
    }
    if (threadIdx.x == 0) g_counts[l] = run + 1;
}

// all 16 layers: rank = base + prefix of (L<=l); OR child bit into flags
__global__ void k_flags_all(int n, int B) {
    __shared__ int s_base[16];
    __shared__ int s_w[16][8];
    int b = blockIdx.x;
    if (threadIdx.x < 16) s_base[threadIdx.x] = g_blk[threadIdx.x * B + b];
    int i = b * TB + threadIdx.x;
    int lane = threadIdx.x & 31, wid = threadIdx.x >> 5;
    bool act = i < n;
    int L = act ? (int)g_L[i] : 100;
    unsigned u = act ? g_sorted[i] : 0u;
    unsigned lm_le = (lane == 31) ? FULLMASK : ((2u << lane) - 1);

    unsigned bal[16];
    #pragma unroll
    for (int l = 0; l < 16; l++) {
        bal[l] = __ballot_sync(FULLMASK, L <= l);
        if (lane == 0) s_w[l][wid] = __popc(bal[l]);
    }
    __syncthreads();
    if (threadIdx.x < 16) {
        int l = threadIdx.x, run = 0;
        #pragma unroll
        for (int w = 0; w < 8; w++) { int v = s_w[l][w]; s_w[l][w] = run; run += v; }
    }
    __syncthreads();

    #pragma unroll
    for (int l = 0; l < 16; l++) {
        int r = act ? (s_base[l] + s_w[l][wid] + __popc(bal[l] & lm_le))
                    : 0x7fffffff;
        unsigned v = 1u << child_at(u, l);
        #pragma unroll
        for (int o = 1; o < 32; o <<= 1) {
            unsigned uv = __shfl_up_sync(FULLMASK, v, o);
            int ur = __shfl_up_sync(FULLMASK, r, o);
            if (lane >= o && ur == r) v |= uv;
        }
        int rn = __shfl_down_sync(FULLMASK, r, 1);
        if (act && (lane == 31 || rn != r)) {
            size_t byte = (size_t)l * n + r;
            atomicOr(&g_flagsb[byte >> 2], v << ((byte & 3) * 8));
        }
    }
}

// byte-packed flags -> float32 output; block 0 also writes the tail
__global__ void k_out(float* __restrict__ out, int n, size_t words,
                      long long out_size) {
    size_t w = (size_t)blockIdx.x * blockDim.x + threadIdx.x;
    if (w < words) {
        unsigned v = g_flagsb[w];
        float4 f;
        f.x = (float)(v & 0xff);
        f.y = (float)((v >> 8) & 0xff);
        f.z = (float)((v >> 16) & 0xff);
        f.w = (float)(v >> 24);
        ((float4*)out)[w] = f;
    }
    if (blockIdx.x == 0 && threadIdx.x < 70) {
        long long base = (long long)16 * n;
        if (base + 70 <= out_size) {
            int t = threadIdx.x;
            float val;
            if (t < 16)      val = (float)g_counts[t];
            else if (t < 64) val = (float)g_perm[t - 16];
            else if (t < 67) val = g_off[t - 64];
            else             val = g_scl[t - 67];
            out[base + t] = val;
        }
    }
}

// ---------------- launcher ----------------

extern "C" void kernel_launch(void* const* d_in, const int* in_sizes, int n_in,
                              void* d_out, int out_size) {
    const float* X = (const float*)d_in[0];
    int n = in_sizes[0] / 3;
    if (n > NMAX) n = NMAX;
    float* out = (float*)d_out;

    void *p_code, *p_sorted, *p_flagsb, *p_temp;
    cudaGetSymbolAddress(&p_code, g_code);
    cudaGetSymbolAddress(&p_sorted, g_sorted);
    cudaGetSymbolAddress(&p_flagsb, g_flagsb);
    cudaGetSymbolAddress(&p_temp, g_temp);

    int blocks = (n + TB - 1) / TB;
    int B = blocks;

    k_minmax<<<blocks, TB>>>(X, n);
    k_params<<<1, TB>>>(B);
    k_quant<<<blocks, TB>>>(X, n);
    k_perm<<<1, 64>>>(n);
    k_remap<<<blocks, TB>>>(n);

    size_t tb = sizeof(g_temp);
    cub::DeviceRadixSort::SortKeys(p_temp, tb,
                                   (const unsigned int*)p_code,
                                   (unsigned int*)p_sorted,
                                   n, 0, 32, (cudaStream_t)0);

    cudaMemsetAsync(p_flagsb, 0, (size_t)16 * n, 0);
    k_blkcnt<<<blocks, TB>>>(n, B);
    k_blkscan<<<16, TB>>>(B);
    k_flags_all<<<blocks, TB>>>(n, B);

    size_t words = (size_t)16 * n / 4;   // 16n divisible by 4
    int fb = (int)((words + TB - 1) / TB);
    k_out<<<fb, TB>>>(out, n, words, (long long)out_size);
}